// round 13
// baseline (speedup 1.0000x reference)
#include <cuda_runtime.h>
#include <cuda_fp16.h>
#include <cstddef>

typedef unsigned long long u64;
#define Bsz 32
#define Nn  4096
#define Kk  11
#define RW  (Bsz*Kk)
#define SLOTS_ELEMS (RW*256)
#define NB  4
#define NCHUNK 8
#define GRID_F 256

#define MODE_FIRST 0
#define MODE_FULL  1
#define MODE_LAST  2

// ---------------- device scratch ----------------
__device__ __align__(16) __half g_feats16[(size_t)Bsz*Nn*256];
__device__ __align__(16) float  g_slots[SLOTS_ELEMS];
__device__ __align__(16) float  g_qW   [SLOTS_ELEMS];
__device__ __align__(16) float  g_Wqk  [256*256];
__device__ __align__(16) float  g_WihT [256*768];
__device__ __align__(16) float  g_WhhT [256*768];
__device__ __align__(16) float  g_asum_part[RW*NCHUNK];
__device__ __align__(16) float  g_updFp[(size_t)NCHUNK*RW*256];

__device__ unsigned g_cnt = 0;
__device__ volatile unsigned g_gen = 0;

__device__ __forceinline__ void gbar(){
    __syncthreads();
    if (threadIdx.x == 0){
        __threadfence();
        unsigned gen = g_gen;
        if (atomicAdd(&g_cnt, 1) == GRID_F - 1){
            g_cnt = 0;
            __threadfence();
            g_gen = gen + 1;
        } else {
            while (g_gen == gen) __nanosleep(64);
        }
        __threadfence();
    }
    __syncthreads();
}

// ---------------- helpers ----------------
__device__ __forceinline__ u64 pk2(float x, float y){
    u64 r; asm("mov.b64 %0,{%1,%2};" : "=l"(r) : "f"(x), "f"(y)); return r;
}
__device__ __forceinline__ float2 upk2(u64 v){
    float2 r; asm("mov.b64 {%0,%1},%2;" : "=f"(r.x), "=f"(r.y) : "l"(v)); return r;
}
__device__ __forceinline__ u64 ffma2(u64 a, u64 b, u64 c){
    u64 d; asm("fma.rn.f32x2 %0,%1,%2,%3;" : "=l"(d) : "l"(a), "l"(b), "l"(c)); return d;
}
__device__ __forceinline__ unsigned sptr(const void* p){
    return (unsigned)__cvta_generic_to_shared(p);
}
__device__ __forceinline__ void mma16816(float& c0, float& c1, float& c2, float& c3,
                                         unsigned a0, unsigned a1, unsigned a2, unsigned a3,
                                         unsigned b0, unsigned b1){
    asm("mma.sync.aligned.m16n8k16.row.col.f32.f16.f16.f32 "
        "{%0,%1,%2,%3},{%4,%5,%6,%7},{%8,%9},{%0,%1,%2,%3};"
        : "+f"(c0), "+f"(c1), "+f"(c2), "+f"(c3)
        : "r"(a0), "r"(a1), "r"(a2), "r"(a3), "r"(b0), "r"(b1));
}
__device__ __forceinline__ void ldmA4(unsigned& r0, unsigned& r1, unsigned& r2, unsigned& r3,
                                      unsigned addr){
    asm volatile("ldmatrix.sync.aligned.m8n8.x4.shared.b16 {%0,%1,%2,%3},[%4];"
        : "=r"(r0), "=r"(r1), "=r"(r2), "=r"(r3) : "r"(addr));
}
__device__ __forceinline__ void ldmB2T(unsigned& r0, unsigned& r1, unsigned addr){
    asm volatile("ldmatrix.sync.aligned.m8n8.x2.trans.shared.b16 {%0,%1},[%2];"
        : "=r"(r0), "=r"(r1) : "r"(addr));
}

// ---------------- LayerNorm of features -> fp16 ----------------
__global__ __launch_bounds__(256) void ln_feat16_k(const float* __restrict__ in,
                                                   const float* __restrict__ gamma,
                                                   const float* __restrict__ beta){
    int warp = threadIdx.x >> 5, lane = threadIdx.x & 31;
    long long row = (long long)blockIdx.x*8 + warp;
    const float4* ip = (const float4*)(in + (size_t)row*256);
    float4 a = ip[lane], b = ip[lane+32];
    float s = a.x+a.y+a.z+a.w + b.x+b.y+b.z+b.w;
    float q = a.x*a.x+a.y*a.y+a.z*a.z+a.w*a.w + b.x*b.x+b.y*b.y+b.z*b.z+b.w*b.w;
    #pragma unroll
    for (int off=16; off; off>>=1){
        s += __shfl_xor_sync(~0u, s, off);
        q += __shfl_xor_sync(~0u, q, off);
    }
    float mean = s*(1.f/256.f);
    float var  = q*(1.f/256.f) - mean*mean;
    float rs   = rsqrtf(var + 1e-5f);
    const float4* gp = (const float4*)gamma; const float4* bp = (const float4*)beta;
    float4 g0 = gp[lane], g1 = gp[lane+32], c0 = bp[lane], c1 = bp[lane+32];
    __half* op = g_feats16 + (size_t)row*256;
    __half2 h01 = __floats2half2_rn((a.x-mean)*rs*g0.x+c0.x, (a.y-mean)*rs*g0.y+c0.y);
    __half2 h23 = __floats2half2_rn((a.z-mean)*rs*g0.z+c0.z, (a.w-mean)*rs*g0.w+c0.w);
    uint2 pk; pk.x = *(unsigned*)&h01; pk.y = *(unsigned*)&h23;
    *(uint2*)(op + lane*4) = pk;
    h01 = __floats2half2_rn((b.x-mean)*rs*g1.x+c1.x, (b.y-mean)*rs*g1.y+c1.y);
    h23 = __floats2half2_rn((b.z-mean)*rs*g1.z+c1.z, (b.w-mean)*rs*g1.w+c1.w);
    pk.x = *(unsigned*)&h01; pk.y = *(unsigned*)&h23;
    *(uint2*)(op + 128 + lane*4) = pk;
}

__global__ void prep_k(const float* __restrict__ Wih, const float* __restrict__ Whh){
    int idx = blockIdx.x*256 + threadIdx.x;
    if (idx < 768*256){
        int k = idx / 768, n = idx % 768;
        g_WihT[idx] = Wih[n*256 + k];
        g_WhhT[idx] = Whh[n*256 + k];
    }
}

// one-time Wqk = Wq @ Wk^T / 16
__global__ __launch_bounds__(256) void gemmT_k(const float* __restrict__ A, const float* __restrict__ B,
                                               float* __restrict__ C, float alpha){
    __shared__ __align__(16) float As[32][36];
    __shared__ __align__(16) float Bs[32][132];
    int tid = threadIdx.x;
    int n0 = blockIdx.x*128, r0 = blockIdx.y*32;
    int lane = tid & 31, rowg = tid >> 5;
    u64 acc01[4] = {0,0,0,0}, acc23[4] = {0,0,0,0};
    for (int kt = 0; kt < 256; kt += 32){
        {
            int r = tid >> 3, kg = (tid & 7) << 2;
            float4 v = *(const float4*)(A + (size_t)(r0+r)*256 + kt + kg);
            As[r][kg]=v.x; As[r][kg+1]=v.y; As[r][kg+2]=v.z; As[r][kg+3]=v.w;
        }
        #pragma unroll
        for (int rep=0; rep<4; rep++){
            int e = rep*256 + tid;
            int n = e >> 3, kc = (e & 7) << 2;
            float4 v = *(const float4*)(B + (size_t)(n0+n)*256 + kt + kc);
            Bs[kc][n]=v.x; Bs[kc+1][n]=v.y; Bs[kc+2][n]=v.z; Bs[kc+3][n]=v.w;
        }
        __syncthreads();
        #pragma unroll
        for (int kk=0; kk<32; kk++){
            float4 bv = *(const float4*)&Bs[kk][lane<<2];
            u64 b01 = pk2(bv.x, bv.y), b23 = pk2(bv.z, bv.w);
            #pragma unroll
            for (int r=0; r<4; r++){
                float av = As[(rowg<<2)+r][kk];
                u64 aa = pk2(av, av);
                acc01[r] = ffma2(aa, b01, acc01[r]);
                acc23[r] = ffma2(aa, b23, acc23[r]);
            }
        }
        __syncthreads();
    }
    #pragma unroll
    for (int r=0; r<4; r++){
        float2 p = upk2(acc01[r]), q = upk2(acc23[r]);
        int row = r0 + (rowg<<2) + r;
        size_t base = (size_t)row*256 + n0 + (lane<<2);
        *(float4*)&C[base] = make_float4(p.x*alpha, p.y*alpha, q.x*alpha, q.y*alpha);
    }
}

// ---------------- pass body (attention) — OWN register allocation ----------------
#define FT_STRIDE 264
#define AT_STRIDE 136
__device__ __noinline__ void pass_body(char* smraw, float* __restrict__ attn_out,
                                       int write_attn){
    __half* ft = (__half*)smraw;
    __half* qs = ft + 128*FT_STRIDE;
    __half* at = qs + 16*FT_STRIDE;
    __shared__ float den[16];
    int b = blockIdx.x >> 3, nc = blockIdx.x & 7;
    int tid = threadIdx.x;
    int lane = tid & 31, w = tid >> 5;
    int gid = lane >> 2, tig = lane & 3;

    for (int e = tid; e < 16*256; e += 256){
        int row = e >> 8, c = e & 255;
        float v = (row < Kk) ? __ldcg(&g_qW[((size_t)b*Kk + row)*256 + c]) : 0.f;
        qs[row*FT_STRIDE + c] = __float2half_rn(v);
    }
    if (tid < 16) den[tid] = 0.f;
    __syncthreads();

    const int c0v = 2*tig, c1v = 2*tig+1, c2v = 8+2*tig, c3v = 9+2*tig;
    const bool v2 = (c2v < Kk), v3 = (c3v < Kk);
    float ls0=0.f, ls1=0.f, ls2=0.f, ls3=0.f;
    float n00=0,n01=0,n02=0,n03=0, n10=0,n11=0,n12=0,n13=0;
    float n20=0,n21=0,n22=0,n23=0, n30=0,n31=0,n32=0,n33=0;

    #pragma unroll 1
    for (int p = 0; p < 4; p++){
        int r0 = nc*512 + p*128;
        #pragma unroll
        for (int i = 0; i < 16; i++){
            int idx = i*256 + tid;
            int row = idx >> 5, c4 = idx & 31;
            uint4 v = *(const uint4*)(g_feats16 + ((size_t)b*Nn + r0 + row)*256 + c4*8);
            *(uint4*)(ft + row*FT_STRIDE + c4*8) = v;
        }
        __syncthreads();

        float cA0=0,cA1=0,cA2=0,cA3=0, cB0=0,cB1=0,cB2=0,cB3=0;
        unsigned a_addr_row = w*16 + (lane & 15);
        #pragma unroll
        for (int ks = 0; ks < 16; ks++){
            unsigned addr = sptr(ft + a_addr_row*FT_STRIDE + ks*16 + ((lane>>4)<<3));
            unsigned a0,a1,a2,a3;
            ldmA4(a0,a1,a2,a3, addr);
            unsigned b0 = *(const unsigned*)(qs + gid*FT_STRIDE + ks*16 + 2*tig);
            unsigned b1 = *(const unsigned*)(qs + gid*FT_STRIDE + ks*16 + 2*tig + 8);
            mma16816(cA0,cA1,cA2,cA3, a0,a1,a2,a3, b0,b1);
            b0 = *(const unsigned*)(qs + (8+gid)*FT_STRIDE + ks*16 + 2*tig);
            b1 = *(const unsigned*)(qs + (8+gid)*FT_STRIDE + ks*16 + 2*tig + 8);
            mma16816(cB0,cB1,cB2,cB3, a0,a1,a2,a3, b0,b1);
        }
        float r0m = fmaxf(cA0, cA1);
        if (v2) r0m = fmaxf(r0m, cB0);
        if (v3) r0m = fmaxf(r0m, cB1);
        float r1m = fmaxf(cA2, cA3);
        if (v2) r1m = fmaxf(r1m, cB2);
        if (v3) r1m = fmaxf(r1m, cB3);
        r0m = fmaxf(r0m, __shfl_xor_sync(~0u, r0m, 1));
        r0m = fmaxf(r0m, __shfl_xor_sync(~0u, r0m, 2));
        r1m = fmaxf(r1m, __shfl_xor_sync(~0u, r1m, 1));
        r1m = fmaxf(r1m, __shfl_xor_sync(~0u, r1m, 2));
        float e0 = __expf(cA0-r0m), e1 = __expf(cA1-r0m);
        float e4 = v2 ? __expf(cB0-r0m) : 0.f, e5 = v3 ? __expf(cB1-r0m) : 0.f;
        float e2 = __expf(cA2-r1m), e3 = __expf(cA3-r1m);
        float e6 = v2 ? __expf(cB2-r1m) : 0.f, e7 = v3 ? __expf(cB3-r1m) : 0.f;
        float s0 = e0+e1+e4+e5, s1 = e2+e3+e6+e7;
        s0 += __shfl_xor_sync(~0u, s0, 1); s0 += __shfl_xor_sync(~0u, s0, 2);
        s1 += __shfl_xor_sync(~0u, s1, 1); s1 += __shfl_xor_sync(~0u, s1, 2);
        float i0 = 1.f/s0, i1 = 1.f/s1;
        e0*=i0; e1*=i0; e4*=i0; e5*=i0;
        e2*=i1; e3*=i1; e6*=i1; e7*=i1;
        int nl0 = w*16 + gid, nl1 = nl0 + 8;
        at[c0v*AT_STRIDE + nl0] = __float2half_rn(e0);
        at[c1v*AT_STRIDE + nl0] = __float2half_rn(e1);
        at[c0v*AT_STRIDE + nl1] = __float2half_rn(e2);
        at[c1v*AT_STRIDE + nl1] = __float2half_rn(e3);
        at[c2v*AT_STRIDE + nl0] = __float2half_rn(e4);
        at[c3v*AT_STRIDE + nl0] = __float2half_rn(e5);
        at[c2v*AT_STRIDE + nl1] = __float2half_rn(e6);
        at[c3v*AT_STRIDE + nl1] = __float2half_rn(e7);
        if (write_attn){
            int n_r0 = r0 + nl0, n_r1 = r0 + nl1;
            size_t ab = (size_t)b*Kk*Nn;
            attn_out[ab + (size_t)c0v*Nn + n_r0] = e0;
            attn_out[ab + (size_t)c1v*Nn + n_r0] = e1;
            attn_out[ab + (size_t)c0v*Nn + n_r1] = e2;
            attn_out[ab + (size_t)c1v*Nn + n_r1] = e3;
            if (v2){ attn_out[ab + (size_t)c2v*Nn + n_r0] = e4; attn_out[ab + (size_t)c2v*Nn + n_r1] = e6; }
            if (v3){ attn_out[ab + (size_t)c3v*Nn + n_r0] = e5; attn_out[ab + (size_t)c3v*Nn + n_r1] = e7; }
        }
        ls0 += e0 + e2; ls1 += e1 + e3; ls2 += e4 + e6; ls3 += e5 + e7;
        __syncthreads();

        #pragma unroll
        for (int k16 = 0; k16 < 8; k16++){
            unsigned aaddr = sptr(at + (lane & 15)*AT_STRIDE + k16*16 + ((lane>>4)<<3));
            unsigned a0,a1,a2,a3;
            ldmA4(a0,a1,a2,a3, aaddr);
            int ln = k16*16 + (lane & 15);
            unsigned base = sptr(ft + ln*FT_STRIDE + w*32);
            unsigned b0, b1;
            ldmB2T(b0,b1, base);        mma16816(n00,n01,n02,n03, a0,a1,a2,a3, b0,b1);
            ldmB2T(b0,b1, base + 16);   mma16816(n10,n11,n12,n13, a0,a1,a2,a3, b0,b1);
            ldmB2T(b0,b1, base + 32);   mma16816(n20,n21,n22,n23, a0,a1,a2,a3, b0,b1);
            ldmB2T(b0,b1, base + 48);   mma16816(n30,n31,n32,n33, a0,a1,a2,a3, b0,b1);
        }
        __syncthreads();
    }

    #pragma unroll
    for (int off = 4; off < 32; off <<= 1){
        ls0 += __shfl_xor_sync(~0u, ls0, off);
        ls1 += __shfl_xor_sync(~0u, ls1, off);
        ls2 += __shfl_xor_sync(~0u, ls2, off);
        ls3 += __shfl_xor_sync(~0u, ls3, off);
    }
    if (gid == 0){
        atomicAdd(&den[c0v], ls0);
        atomicAdd(&den[c1v], ls1);
        if (v2) atomicAdd(&den[c2v], ls2);
        if (v3) atomicAdd(&den[c3v], ls3);
    }
    __syncthreads();
    if (tid < Kk) g_asum_part[(b*Kk+tid)*NCHUNK + nc] = den[tid];

    float* dst = g_updFp + (size_t)nc*RW*256;
    if (gid < Kk){
        size_t base = (size_t)(b*Kk+gid)*256 + w*32 + 2*tig;
        *(float2*)&dst[base     ] = make_float2(n00,n01);
        *(float2*)&dst[base +  8] = make_float2(n10,n11);
        *(float2*)&dst[base + 16] = make_float2(n20,n21);
        *(float2*)&dst[base + 24] = make_float2(n30,n31);
    }
    if (gid + 8 < Kk){
        size_t base = (size_t)(b*Kk+gid+8)*256 + w*32 + 2*tig;
        *(float2*)&dst[base     ] = make_float2(n02,n03);
        *(float2*)&dst[base +  8] = make_float2(n12,n13);
        *(float2*)&dst[base + 16] = make_float2(n22,n23);
        *(float2*)&dst[base + 24] = make_float2(n32,n33);
    }
    __syncthreads();
}

// ---------------- slot-update body — OWN register allocation ----------------
__device__ __forceinline__ void mgemm(const float* __restrict__ x, int xst,
                                      const float* __restrict__ W, int K, int N,
                                      float* out, int ost, const float* __restrict__ bias,
                                      bool relu, float* Wt){
    int tid = threadIdx.x;
    int j = tid >> 6, cc = (tid & 63) << 2;
    for (int n0 = 0; n0 < N; n0 += 256){
        u64 a0=0,a1=0,b0=0,b1=0;
        float4 pf[8];
        #pragma unroll
        for (int r=0;r<8;r++){
            int e = r*256 + tid; int kk = e>>6; int c4 = (e&63)<<2;
            pf[r] = *(const float4*)&W[(size_t)kk*N + n0 + c4];
        }
        for (int k0 = 0; k0 < K; k0 += 32){
            __syncthreads();
            #pragma unroll
            for (int r=0;r<8;r++){
                int e = r*256 + tid; int kk = e>>6; int c4 = (e&63)<<2;
                *(float4*)&Wt[kk*260 + c4] = pf[r];
            }
            __syncthreads();
            if (k0 + 32 < K){
                #pragma unroll
                for (int r=0;r<8;r++){
                    int e = r*256 + tid; int kk = e>>6; int c4 = (e&63)<<2;
                    pf[r] = *(const float4*)&W[(size_t)(k0+32+kk)*N + n0 + c4];
                }
            }
            #pragma unroll
            for (int kk=0; kk<32; kk+=2){
                float xv0 = x[j*xst + k0 + kk], xv1 = x[j*xst + k0 + kk + 1];
                float4 w0v = *(const float4*)&Wt[kk*260 + cc];
                float4 w1v = *(const float4*)&Wt[(kk+1)*260 + cc];
                u64 aa0 = pk2(xv0,xv0), aa1 = pk2(xv1,xv1);
                a0 = ffma2(aa0, pk2(w0v.x,w0v.y), a0);
                a1 = ffma2(aa0, pk2(w0v.z,w0v.w), a1);
                b0 = ffma2(aa1, pk2(w1v.x,w1v.y), b0);
                b1 = ffma2(aa1, pk2(w1v.z,w1v.w), b1);
            }
        }
        float2 pa = upk2(a0), pb = upk2(b0), qa = upk2(a1), qb = upk2(b1);
        float4 o = make_float4(pa.x+pb.x, pa.y+pb.y, qa.x+qb.x, qa.y+qb.y);
        if (bias){
            float4 bv = *(const float4*)&bias[n0+cc];
            o.x+=bv.x; o.y+=bv.y; o.z+=bv.z; o.w+=bv.w;
        }
        if (relu){ o.x=fmaxf(o.x,0.f); o.y=fmaxf(o.y,0.f); o.z=fmaxf(o.z,0.f); o.w=fmaxf(o.w,0.f); }
        *(float4*)&out[(size_t)j*ost + n0 + cc] = o;
    }
    __syncthreads();
}

__device__ __forceinline__ void lnRow(const float* in, float* out,
                                      const float* __restrict__ gamma,
                                      const float* __restrict__ beta){
    int w = threadIdx.x >> 5, lane = threadIdx.x & 31;
    if (w < 4){
        const float* ip = in + w*264;
        float4 a = *(const float4*)&ip[lane<<2];
        float4 b = *(const float4*)&ip[128 + (lane<<2)];
        float s = a.x+a.y+a.z+a.w + b.x+b.y+b.z+b.w;
        float q = a.x*a.x+a.y*a.y+a.z*a.z+a.w*a.w + b.x*b.x+b.y*b.y+b.z*b.z+b.w*b.w;
        #pragma unroll
        for (int off=16; off; off>>=1){
            s += __shfl_xor_sync(~0u, s, off);
            q += __shfl_xor_sync(~0u, q, off);
        }
        float mean = s*(1.f/256.f);
        float var  = q*(1.f/256.f) - mean*mean;
        float rs   = rsqrtf(var + 1e-5f);
        float4 g0 = *(const float4*)&gamma[lane<<2], g1 = *(const float4*)&gamma[128+(lane<<2)];
        float4 c0 = *(const float4*)&beta[lane<<2],  c1 = *(const float4*)&beta[128+(lane<<2)];
        float* op = out + w*264;
        *(float4*)&op[lane<<2] = make_float4((a.x-mean)*rs*g0.x+c0.x, (a.y-mean)*rs*g0.y+c0.y,
                                             (a.z-mean)*rs*g0.z+c0.z, (a.w-mean)*rs*g0.w+c0.w);
        *(float4*)&op[128+(lane<<2)] = make_float4((b.x-mean)*rs*g1.x+c1.x, (b.y-mean)*rs*g1.y+c1.y,
                                                   (b.z-mean)*rs*g1.z+c1.z, (b.w-mean)*rs*g1.w+c1.w);
    }
    __syncthreads();
}

__device__ __noinline__ void k3_body(char* smraw, int mode,
        const float* __restrict__ z, const float* __restrict__ w0, const float* __restrict__ sigma,
        const float* __restrict__ gs, const float* __restrict__ bs,
        const float* __restrict__ gm, const float* __restrict__ bm,
        const float* __restrict__ Wv,
        const float* __restrict__ bih, const float* __restrict__ bhh,
        const float* __restrict__ W1, const float* __restrict__ b1,
        const float* __restrict__ W2, const float* __restrict__ b2,
        float* __restrict__ out){
    float* sm  = (float*)smraw;
    float* xs  = sm;
    float* hh  = xs + 1056;
    float* us  = hh + 1056;
    float* gi  = us + 1056;
    float* gh  = gi + 3104;
    float* hid = gh + 3104;
    float* Wt  = hid + 4128;
    __shared__ float dinv[NB];
    int tid = threadIdx.x, r0 = blockIdx.x*NB;

    if (mode == MODE_FIRST){
        float sig = sigma[0];
        for (int u = tid; u < 1024; u += 256){
            int j = u>>8, c = u&255, row = r0 + j;
            float wv = w0[(row % Kk)*256 + c];
            float v = wv + z[row*256 + c]*sig*wv;
            hh[j*264 + c] = v;
            g_slots[row*256 + c] = v;
        }
        __syncthreads();
        lnRow(hh, xs, gs, bs);
        mgemm(xs, 264, g_Wqk, 256, 256, g_qW + (size_t)r0*256, 256, nullptr, false, Wt);
        return;
    }

    if (tid < NB){
        float s = 0.f;
        #pragma unroll
        for (int p=0;p<NCHUNK;p++) s += __ldcg(&g_asum_part[(r0+tid)*NCHUNK + p]);
        dinv[tid] = 1.f/(s + 1e-6f);
    }
    __syncthreads();
    for (int u = tid; u < 1024; u += 256){
        float s = 0.f;
        #pragma unroll
        for (int p=0;p<NCHUNK;p++) s += __ldcg(&g_updFp[(size_t)p*RW*256 + (size_t)r0*256 + u]);
        int j = u>>8, c = u&255;
        xs[j*264 + c] = s * dinv[j];
        hh[j*264 + c] = g_slots[r0*256 + u];
    }
    __syncthreads();
    mgemm(xs, 264, Wv, 256, 256, us, 264, nullptr, false, Wt);
    mgemm(us, 264, g_WihT, 256, 768, gi, 776, bih, false, Wt);
    mgemm(hh, 264, g_WhhT, 256, 768, gh, 776, bhh, false, Wt);
    for (int u = tid; u < 1024; u += 256){
        int j = u>>8, c = u&255;
        float r  = 1.f/(1.f + __expf(-(gi[j*776 + c]     + gh[j*776 + c])));
        float zg = 1.f/(1.f + __expf(-(gi[j*776 + 256+c] + gh[j*776 + 256+c])));
        float nn = tanhf(gi[j*776 + 512+c] + r*gh[j*776 + 512+c]);
        hh[j*264 + c] = (1.f - zg)*nn + zg*hh[j*264 + c];
    }
    __syncthreads();
    lnRow(hh, xs, gm, bm);
    mgemm(xs, 264, W1, 256, 1024, hid, 1032, b1, true, Wt);
    mgemm(hid, 1032, W2, 1024, 256, us, 264, b2, false, Wt);
    for (int u = tid; u < 1024; u += 256){
        int j = u>>8, c = u&255;
        float v = hh[j*264 + c] + us[j*264 + c];
        hh[j*264 + c] = v;
        g_slots[r0*256 + u] = v;
        if (mode == MODE_LAST) out[r0*256 + u] = v;
    }
    __syncthreads();
    if (mode != MODE_LAST){
        lnRow(hh, xs, gs, bs);
        mgemm(xs, 264, g_Wqk, 256, 256, g_qW + (size_t)r0*256, 256, nullptr, false, Wt);
    }
}

// ---------------- fused persistent kernel ----------------
__global__ void __launch_bounds__(256, 2) fused_k(
        const float* __restrict__ z, const float* __restrict__ w0, const float* __restrict__ sigma,
        const float* __restrict__ gs, const float* __restrict__ bs,
        const float* __restrict__ gm, const float* __restrict__ bm,
        const float* __restrict__ Wv,
        const float* __restrict__ bih, const float* __restrict__ bhh,
        const float* __restrict__ W1, const float* __restrict__ b1,
        const float* __restrict__ W2, const float* __restrict__ b2,
        float* __restrict__ out){
    extern __shared__ __align__(16) char smraw[];
    float* attn_out = out + SLOTS_ELEMS;

    if (blockIdx.x < RW/NB)
        k3_body(smraw, MODE_FIRST, z, w0, sigma, gs, bs, gm, bm,
                Wv, bih, bhh, W1, b1, W2, b2, out);
    gbar();
    #pragma unroll 1
    for (int it = 0; it < 3; it++){
        pass_body(smraw, attn_out, it==2 ? 1 : 0);
        gbar();
        if (blockIdx.x < RW/NB)
            k3_body(smraw, it==2 ? MODE_LAST : MODE_FULL, z, w0, sigma, gs, bs, gm, bm,
                    Wv, bih, bhh, W1, b1, W2, b2, out);
        if (it < 2) gbar();
    }
}

// ---------------- host ----------------
extern "C" void kernel_launch(void* const* d_in, const int* in_sizes, int n_in,
                              void* d_out, int out_size){
    const float* features=(const float*)d_in[0];
    const float* sigma=(const float*)d_in[1];
    const float* z   =(const float*)d_in[2];
    const float* w0  =(const float*)d_in[3];
    const float* gf  =(const float*)d_in[4];  const float* bf =(const float*)d_in[5];
    const float* gs  =(const float*)d_in[6];  const float* bs =(const float*)d_in[7];
    const float* gm  =(const float*)d_in[8];  const float* bm =(const float*)d_in[9];
    const float* Wk  =(const float*)d_in[10]; const float* Wv =(const float*)d_in[11];
    const float* Wq  =(const float*)d_in[12];
    const float* Wih =(const float*)d_in[13]; const float* Whh=(const float*)d_in[14];
    const float* bih =(const float*)d_in[15]; const float* bhh=(const float*)d_in[16];
    const float* W1  =(const float*)d_in[17]; const float* b1 =(const float*)d_in[18];
    const float* W2  =(const float*)d_in[19]; const float* b2 =(const float*)d_in[20];
    float* out = (float*)d_out;

    float* wqk;
    cudaGetSymbolAddress((void**)&wqk, g_Wqk);

    const int fSmem = 21824*4;   // 87,296 B
    cudaFuncSetAttribute(fused_k, cudaFuncAttributeMaxDynamicSharedMemorySize, fSmem);

    static cudaStream_t s2 = nullptr;
    static cudaEvent_t  e0 = nullptr, e2 = nullptr;
    if (!s2){
        cudaStreamCreateWithFlags(&s2, cudaStreamNonBlocking);
        cudaEventCreateWithFlags(&e0, cudaEventDisableTiming);
        cudaEventCreateWithFlags(&e2, cudaEventDisableTiming);
    }

    cudaEventRecord(e0, 0);
    cudaStreamWaitEvent(s2, e0, 0);
    gemmT_k<<<dim3(2,8,1),256,0,s2>>>(Wq, Wk, wqk, 1.f/16.f);   // 0
    prep_k<<<768,256,0,s2>>>(Wih, Whh);                          // 1
    cudaEventRecord(e2, s2);

    ln_feat16_k<<<16384,256>>>(features, gf, bf);                // 2

    cudaStreamWaitEvent(0, e2, 0);

    fused_k<<<GRID_F,256,fSmem>>>(z, w0, sigma, gs, bs, gm, bm,  // 3 <- profiled
                                  Wv, bih, bhh, W1, b1, W2, b2, out);
}

// round 15
// speedup vs baseline: 1.2564x; 1.2564x over previous
#include <cuda_runtime.h>
#include <cuda_fp16.h>
#include <cstddef>

typedef unsigned long long u64;
#define Bsz 32
#define Nn  4096
#define Kk  11
#define RW  (Bsz*Kk)
#define SLOTS_ELEMS (RW*256)
#define NB  4
#define K3_BLOCKS (RW/NB)
#define NCHUNK 8

#define MODE_FIRST 0
#define MODE_FULL  1
#define MODE_LAST  2

// ---------------- device scratch ----------------
__device__ __align__(16) __half g_feats16[(size_t)Bsz*Nn*256];
__device__ __align__(16) float  g_slots[SLOTS_ELEMS];
__device__ __align__(16) float  g_qW   [SLOTS_ELEMS];
__device__ __align__(16) __half g_Wqk16 [256*256];
__device__ __align__(16) __half g_Wv16  [256*256];
__device__ __align__(16) __half g_WihT16[256*768];
__device__ __align__(16) __half g_WhhT16[256*768];
__device__ __align__(16) __half g_W116  [256*1024];
__device__ __align__(16) __half g_W216  [1024*256];
__device__ __align__(16) float  g_asum_part[RW*NCHUNK];
__device__ __align__(16) float  g_updFp[(size_t)NCHUNK*RW*256];

// ---------------- helpers ----------------
__device__ __forceinline__ u64 pk2(float x, float y){
    u64 r; asm("mov.b64 %0,{%1,%2};" : "=l"(r) : "f"(x), "f"(y)); return r;
}
__device__ __forceinline__ float2 upk2(u64 v){
    float2 r; asm("mov.b64 {%0,%1},%2;" : "=f"(r.x), "=f"(r.y) : "l"(v)); return r;
}
__device__ __forceinline__ u64 ffma2(u64 a, u64 b, u64 c){
    u64 d; asm("fma.rn.f32x2 %0,%1,%2,%3;" : "=l"(d) : "l"(a), "l"(b), "l"(c)); return d;
}
__device__ __forceinline__ unsigned sptr(const void* p){
    return (unsigned)__cvta_generic_to_shared(p);
}
__device__ __forceinline__ void mma16816(float& c0, float& c1, float& c2, float& c3,
                                         unsigned a0, unsigned a1, unsigned a2, unsigned a3,
                                         unsigned b0, unsigned b1){
    asm("mma.sync.aligned.m16n8k16.row.col.f32.f16.f16.f32 "
        "{%0,%1,%2,%3},{%4,%5,%6,%7},{%8,%9},{%0,%1,%2,%3};"
        : "+f"(c0), "+f"(c1), "+f"(c2), "+f"(c3)
        : "r"(a0), "r"(a1), "r"(a2), "r"(a3), "r"(b0), "r"(b1));
}
__device__ __forceinline__ void ldmA4(unsigned& r0, unsigned& r1, unsigned& r2, unsigned& r3,
                                      unsigned addr){
    asm volatile("ldmatrix.sync.aligned.m8n8.x4.shared.b16 {%0,%1,%2,%3},[%4];"
        : "=r"(r0), "=r"(r1), "=r"(r2), "=r"(r3) : "r"(addr));
}
__device__ __forceinline__ void ldmB2T(unsigned& r0, unsigned& r1, unsigned addr){
    asm volatile("ldmatrix.sync.aligned.m8n8.x2.trans.shared.b16 {%0,%1},[%2];"
        : "=r"(r0), "=r"(r1) : "r"(addr));
}

// ---------------- LayerNorm of features -> fp16 ----------------
__global__ __launch_bounds__(256) void ln_feat16_k(const float* __restrict__ in,
                                                   const float* __restrict__ gamma,
                                                   const float* __restrict__ beta){
    int warp = threadIdx.x >> 5, lane = threadIdx.x & 31;
    long long row = (long long)blockIdx.x*8 + warp;
    const float4* ip = (const float4*)(in + (size_t)row*256);
    float4 a = ip[lane], b = ip[lane+32];
    float s = a.x+a.y+a.z+a.w + b.x+b.y+b.z+b.w;
    float q = a.x*a.x+a.y*a.y+a.z*a.z+a.w*a.w + b.x*b.x+b.y*b.y+b.z*b.z+b.w*b.w;
    #pragma unroll
    for (int off=16; off; off>>=1){
        s += __shfl_xor_sync(~0u, s, off);
        q += __shfl_xor_sync(~0u, q, off);
    }
    float mean = s*(1.f/256.f);
    float var  = q*(1.f/256.f) - mean*mean;
    float rs   = rsqrtf(var + 1e-5f);
    const float4* gp = (const float4*)gamma; const float4* bp = (const float4*)beta;
    float4 g0 = gp[lane], g1 = gp[lane+32], c0 = bp[lane], c1 = bp[lane+32];
    __half* op = g_feats16 + (size_t)row*256;
    __half2 h01 = __floats2half2_rn((a.x-mean)*rs*g0.x+c0.x, (a.y-mean)*rs*g0.y+c0.y);
    __half2 h23 = __floats2half2_rn((a.z-mean)*rs*g0.z+c0.z, (a.w-mean)*rs*g0.w+c0.w);
    uint2 pk; pk.x = *(unsigned*)&h01; pk.y = *(unsigned*)&h23;
    *(uint2*)(op + lane*4) = pk;
    h01 = __floats2half2_rn((b.x-mean)*rs*g1.x+c1.x, (b.y-mean)*rs*g1.y+c1.y);
    h23 = __floats2half2_rn((b.z-mean)*rs*g1.z+c1.z, (b.w-mean)*rs*g1.w+c1.w);
    pk.x = *(unsigned*)&h01; pk.y = *(unsigned*)&h23;
    *(uint2*)(op + 128 + lane*4) = pk;
}

// weight conversion/transpose to fp16 (hidden under LN on side stream)
__global__ void prep_k(const float* __restrict__ Wih, const float* __restrict__ Whh,
                       const float* __restrict__ Wv,  const float* __restrict__ W1,
                       const float* __restrict__ W2){
    int idx = blockIdx.x*256 + threadIdx.x;   // grid 1024*256 = 262144
    if (idx < 196608){
        int k = idx / 768, n = idx % 768;
        g_WihT16[idx] = __float2half_rn(Wih[n*256 + k]);
        g_WhhT16[idx] = __float2half_rn(Whh[n*256 + k]);
    }
    if (idx < 65536) g_Wv16[idx] = __float2half_rn(Wv[idx]);
    if (idx < 262144){
        g_W116[idx] = __float2half_rn(W1[idx]);
        g_W216[idx] = __float2half_rn(W2[idx]);
    }
}

// Wqk16 = fp16(Wq @ Wk^T / 16), 256 blocks, 16x16 tile each
__global__ __launch_bounds__(256) void gemmT16_k(const float* __restrict__ Wq,
                                                 const float* __restrict__ Wk){
    __shared__ __align__(16) float As[16*260];
    __shared__ __align__(16) float Bs[16*260];
    int bx = blockIdx.x;
    int rt = (bx >> 4) * 16, nt = (bx & 15) * 16;
    int tid = threadIdx.x;
    for (int i = tid; i < 1024; i += 256){
        int row = i >> 6, c4 = (i & 63) << 2;
        *(float4*)&As[row*260 + c4] = *(const float4*)&Wq[(size_t)(rt+row)*256 + c4];
        *(float4*)&Bs[row*260 + c4] = *(const float4*)&Wk[(size_t)(nt+row)*256 + c4];
    }
    __syncthreads();
    int r = tid >> 4, n = tid & 15;
    const float4* ar = (const float4*)&As[r*260];
    const float4* br = (const float4*)&Bs[n*260];
    float acc = 0.f;
    #pragma unroll 16
    for (int k4 = 0; k4 < 64; k4++){
        float4 a = ar[k4], b = br[k4];
        acc += a.x*b.x + a.y*b.y + a.z*b.z + a.w*b.w;
    }
    g_Wqk16[(size_t)(rt+r)*256 + nt + n] = __float2half_rn(acc * (1.f/16.f));
}

// ---------------- fused attention pass (R11 structure, validated) ----------------
#define FT_STRIDE 264
#define AT_STRIDE 136
__global__ __launch_bounds__(256) void passAB_k(float* __restrict__ attn_out, int write_attn){
    extern __shared__ __align__(16) __half sa[];
    __half* ft = sa;
    __half* qs = sa + 128*FT_STRIDE;
    __half* at = qs + 16*FT_STRIDE;
    __shared__ float den[16];
    int b = blockIdx.x, nc = blockIdx.y, tid = threadIdx.x;
    int lane = tid & 31, w = tid >> 5;
    int gid = lane >> 2, tig = lane & 3;

    for (int e = tid; e < 16*256; e += 256){
        int row = e >> 8, c = e & 255;
        float v = (row < Kk) ? g_qW[((size_t)b*Kk + row)*256 + c] : 0.f;
        qs[row*FT_STRIDE + c] = __float2half_rn(v);
    }
    if (tid < 16) den[tid] = 0.f;
    __syncthreads();

    const int c0v = 2*tig, c1v = 2*tig+1, c2v = 8+2*tig, c3v = 9+2*tig;
    const bool v2 = (c2v < Kk), v3 = (c3v < Kk);
    float ls0=0.f, ls1=0.f, ls2=0.f, ls3=0.f;
    float n00=0,n01=0,n02=0,n03=0, n10=0,n11=0,n12=0,n13=0;
    float n20=0,n21=0,n22=0,n23=0, n30=0,n31=0,n32=0,n33=0;

    #pragma unroll 1
    for (int p = 0; p < 4; p++){
        int r0 = nc*512 + p*128;
        #pragma unroll
        for (int i = 0; i < 16; i++){
            int idx = i*256 + tid;
            int row = idx >> 5, c4 = idx & 31;
            uint4 v = *(const uint4*)(g_feats16 + ((size_t)b*Nn + r0 + row)*256 + c4*8);
            *(uint4*)(ft + row*FT_STRIDE + c4*8) = v;
        }
        __syncthreads();

        float cA0=0,cA1=0,cA2=0,cA3=0, cB0=0,cB1=0,cB2=0,cB3=0;
        unsigned a_addr_row = w*16 + (lane & 15);
        #pragma unroll
        for (int ks = 0; ks < 16; ks++){
            unsigned addr = sptr(ft + a_addr_row*FT_STRIDE + ks*16 + ((lane>>4)<<3));
            unsigned a0,a1,a2,a3;
            ldmA4(a0,a1,a2,a3, addr);
            unsigned b0 = *(const unsigned*)(qs + gid*FT_STRIDE + ks*16 + 2*tig);
            unsigned b1 = *(const unsigned*)(qs + gid*FT_STRIDE + ks*16 + 2*tig + 8);
            mma16816(cA0,cA1,cA2,cA3, a0,a1,a2,a3, b0,b1);
            b0 = *(const unsigned*)(qs + (8+gid)*FT_STRIDE + ks*16 + 2*tig);
            b1 = *(const unsigned*)(qs + (8+gid)*FT_STRIDE + ks*16 + 2*tig + 8);
            mma16816(cB0,cB1,cB2,cB3, a0,a1,a2,a3, b0,b1);
        }
        float r0m = fmaxf(cA0, cA1);
        if (v2) r0m = fmaxf(r0m, cB0);
        if (v3) r0m = fmaxf(r0m, cB1);
        float r1m = fmaxf(cA2, cA3);
        if (v2) r1m = fmaxf(r1m, cB2);
        if (v3) r1m = fmaxf(r1m, cB3);
        r0m = fmaxf(r0m, __shfl_xor_sync(~0u, r0m, 1));
        r0m = fmaxf(r0m, __shfl_xor_sync(~0u, r0m, 2));
        r1m = fmaxf(r1m, __shfl_xor_sync(~0u, r1m, 1));
        r1m = fmaxf(r1m, __shfl_xor_sync(~0u, r1m, 2));
        float e0 = __expf(cA0-r0m), e1 = __expf(cA1-r0m);
        float e4 = v2 ? __expf(cB0-r0m) : 0.f, e5 = v3 ? __expf(cB1-r0m) : 0.f;
        float e2 = __expf(cA2-r1m), e3 = __expf(cA3-r1m);
        float e6 = v2 ? __expf(cB2-r1m) : 0.f, e7 = v3 ? __expf(cB3-r1m) : 0.f;
        float s0 = e0+e1+e4+e5, s1 = e2+e3+e6+e7;
        s0 += __shfl_xor_sync(~0u, s0, 1); s0 += __shfl_xor_sync(~0u, s0, 2);
        s1 += __shfl_xor_sync(~0u, s1, 1); s1 += __shfl_xor_sync(~0u, s1, 2);
        float i0 = 1.f/s0, i1 = 1.f/s1;
        e0*=i0; e1*=i0; e4*=i0; e5*=i0;
        e2*=i1; e3*=i1; e6*=i1; e7*=i1;
        int nl0 = w*16 + gid, nl1 = nl0 + 8;
        at[c0v*AT_STRIDE + nl0] = __float2half_rn(e0);
        at[c1v*AT_STRIDE + nl0] = __float2half_rn(e1);
        at[c0v*AT_STRIDE + nl1] = __float2half_rn(e2);
        at[c1v*AT_STRIDE + nl1] = __float2half_rn(e3);
        at[c2v*AT_STRIDE + nl0] = __float2half_rn(e4);
        at[c3v*AT_STRIDE + nl0] = __float2half_rn(e5);
        at[c2v*AT_STRIDE + nl1] = __float2half_rn(e6);
        at[c3v*AT_STRIDE + nl1] = __float2half_rn(e7);
        if (write_attn){
            int n_r0 = r0 + nl0, n_r1 = r0 + nl1;
            size_t ab = (size_t)b*Kk*Nn;
            attn_out[ab + (size_t)c0v*Nn + n_r0] = e0;
            attn_out[ab + (size_t)c1v*Nn + n_r0] = e1;
            attn_out[ab + (size_t)c0v*Nn + n_r1] = e2;
            attn_out[ab + (size_t)c1v*Nn + n_r1] = e3;
            if (v2){ attn_out[ab + (size_t)c2v*Nn + n_r0] = e4; attn_out[ab + (size_t)c2v*Nn + n_r1] = e6; }
            if (v3){ attn_out[ab + (size_t)c3v*Nn + n_r0] = e5; attn_out[ab + (size_t)c3v*Nn + n_r1] = e7; }
        }
        ls0 += e0 + e2; ls1 += e1 + e3; ls2 += e4 + e6; ls3 += e5 + e7;
        __syncthreads();

        #pragma unroll
        for (int k16 = 0; k16 < 8; k16++){
            unsigned aaddr = sptr(at + (lane & 15)*AT_STRIDE + k16*16 + ((lane>>4)<<3));
            unsigned a0,a1,a2,a3;
            ldmA4(a0,a1,a2,a3, aaddr);
            int ln = k16*16 + (lane & 15);
            unsigned base = sptr(ft + ln*FT_STRIDE + w*32);
            unsigned b0, b1;
            ldmB2T(b0,b1, base);        mma16816(n00,n01,n02,n03, a0,a1,a2,a3, b0,b1);
            ldmB2T(b0,b1, base + 16);   mma16816(n10,n11,n12,n13, a0,a1,a2,a3, b0,b1);
            ldmB2T(b0,b1, base + 32);   mma16816(n20,n21,n22,n23, a0,a1,a2,a3, b0,b1);
            ldmB2T(b0,b1, base + 48);   mma16816(n30,n31,n32,n33, a0,a1,a2,a3, b0,b1);
        }
        __syncthreads();
    }

    #pragma unroll
    for (int off = 4; off < 32; off <<= 1){
        ls0 += __shfl_xor_sync(~0u, ls0, off);
        ls1 += __shfl_xor_sync(~0u, ls1, off);
        ls2 += __shfl_xor_sync(~0u, ls2, off);
        ls3 += __shfl_xor_sync(~0u, ls3, off);
    }
    if (gid == 0){
        atomicAdd(&den[c0v], ls0);
        atomicAdd(&den[c1v], ls1);
        if (v2) atomicAdd(&den[c2v], ls2);
        if (v3) atomicAdd(&den[c3v], ls3);
    }
    __syncthreads();
    if (tid < Kk) g_asum_part[(b*Kk+tid)*NCHUNK + nc] = den[tid];

    float* dst = g_updFp + (size_t)nc*RW*256;
    if (gid < Kk){
        size_t base = (size_t)(b*Kk+gid)*256 + w*32 + 2*tig;
        *(float2*)&dst[base     ] = make_float2(n00,n01);
        *(float2*)&dst[base +  8] = make_float2(n10,n11);
        *(float2*)&dst[base + 16] = make_float2(n20,n21);
        *(float2*)&dst[base + 24] = make_float2(n30,n31);
    }
    if (gid + 8 < Kk){
        size_t base = (size_t)(b*Kk+gid+8)*256 + w*32 + 2*tig;
        *(float2*)&dst[base     ] = make_float2(n02,n03);
        *(float2*)&dst[base +  8] = make_float2(n12,n13);
        *(float2*)&dst[base + 16] = make_float2(n22,n23);
        *(float2*)&dst[base + 24] = make_float2(n32,n33);
    }
}

// ---------------- fused slot-update with fp16 weights ----------------
__device__ __forceinline__ void mgemm16(const float* __restrict__ x, int xst,
                                        const __half* __restrict__ W, int K, int N,
                                        float* out, int ost, const float* __restrict__ bias,
                                        bool relu, __half* Wt){
    int tid = threadIdx.x;
    int j = tid >> 6, cc = (tid & 63) << 2;
    for (int n0 = 0; n0 < N; n0 += 256){
        u64 a0=0,a1=0,b0=0,b1=0;
        uint2 pf[8];
        #pragma unroll
        for (int r=0;r<8;r++){
            int e = r*256 + tid; int kk = e>>6; int c4 = (e&63)<<2;
            pf[r] = *(const uint2*)&W[(size_t)kk*N + n0 + c4];
        }
        for (int k0 = 0; k0 < K; k0 += 32){
            __syncthreads();
            #pragma unroll
            for (int r=0;r<8;r++){
                int e = r*256 + tid; int kk = e>>6; int c4 = (e&63)<<2;
                *(uint2*)&Wt[kk*264 + c4] = pf[r];
            }
            __syncthreads();
            if (k0 + 32 < K){
                #pragma unroll
                for (int r=0;r<8;r++){
                    int e = r*256 + tid; int kk = e>>6; int c4 = (e&63)<<2;
                    pf[r] = *(const uint2*)&W[(size_t)(k0+32+kk)*N + n0 + c4];
                }
            }
            #pragma unroll
            for (int kk=0; kk<32; kk+=2){
                float xv0 = x[j*xst + k0 + kk], xv1 = x[j*xst + k0 + kk + 1];
                uint2 hv0 = *(const uint2*)&Wt[kk*264 + cc];
                uint2 hv1 = *(const uint2*)&Wt[(kk+1)*264 + cc];
                float2 f00 = __half22float2(*(__half2*)&hv0.x);
                float2 f01 = __half22float2(*(__half2*)&hv0.y);
                float2 f10 = __half22float2(*(__half2*)&hv1.x);
                float2 f11 = __half22float2(*(__half2*)&hv1.y);
                u64 aa0 = pk2(xv0,xv0), aa1 = pk2(xv1,xv1);
                a0 = ffma2(aa0, pk2(f00.x,f00.y), a0);
                a1 = ffma2(aa0, pk2(f01.x,f01.y), a1);
                b0 = ffma2(aa1, pk2(f10.x,f10.y), b0);
                b1 = ffma2(aa1, pk2(f11.x,f11.y), b1);
            }
        }
        float2 pa = upk2(a0), pb = upk2(b0), qa = upk2(a1), qb = upk2(b1);
        float4 o = make_float4(pa.x+pb.x, pa.y+pb.y, qa.x+qb.x, qa.y+qb.y);
        if (bias){
            float4 bv = *(const float4*)&bias[n0+cc];
            o.x+=bv.x; o.y+=bv.y; o.z+=bv.z; o.w+=bv.w;
        }
        if (relu){ o.x=fmaxf(o.x,0.f); o.y=fmaxf(o.y,0.f); o.z=fmaxf(o.z,0.f); o.w=fmaxf(o.w,0.f); }
        *(float4*)&out[(size_t)j*ost + n0 + cc] = o;
    }
    __syncthreads();
}

__device__ __forceinline__ void lnRow(const float* in, float* out,
                                      const float* __restrict__ gamma,
                                      const float* __restrict__ beta){
    int w = threadIdx.x >> 5, lane = threadIdx.x & 31;
    if (w < 4){
        const float* ip = in + w*264;
        float4 a = *(const float4*)&ip[lane<<2];
        float4 b = *(const float4*)&ip[128 + (lane<<2)];
        float s = a.x+a.y+a.z+a.w + b.x+b.y+b.z+b.w;
        float q = a.x*a.x+a.y*a.y+a.z*a.z+a.w*a.w + b.x*b.x+b.y*b.y+b.z*b.z+b.w*b.w;
        #pragma unroll
        for (int off=16; off; off>>=1){
            s += __shfl_xor_sync(~0u, s, off);
            q += __shfl_xor_sync(~0u, q, off);
        }
        float mean = s*(1.f/256.f);
        float var  = q*(1.f/256.f) - mean*mean;
        float rs   = rsqrtf(var + 1e-5f);
        float4 g0 = *(const float4*)&gamma[lane<<2], g1 = *(const float4*)&gamma[128+(lane<<2)];
        float4 c0 = *(const float4*)&beta[lane<<2],  c1 = *(const float4*)&beta[128+(lane<<2)];
        float* op = out + w*264;
        *(float4*)&op[lane<<2] = make_float4((a.x-mean)*rs*g0.x+c0.x, (a.y-mean)*rs*g0.y+c0.y,
                                             (a.z-mean)*rs*g0.z+c0.z, (a.w-mean)*rs*g0.w+c0.w);
        *(float4*)&op[128+(lane<<2)] = make_float4((b.x-mean)*rs*g1.x+c1.x, (b.y-mean)*rs*g1.y+c1.y,
                                                   (b.z-mean)*rs*g1.z+c1.z, (b.w-mean)*rs*g1.w+c1.w);
    }
    __syncthreads();
}

__global__ __launch_bounds__(256) void k3_k(int mode,
        const float* __restrict__ z, const float* __restrict__ w0, const float* __restrict__ sigma,
        const float* __restrict__ gs, const float* __restrict__ bs,
        const float* __restrict__ gm, const float* __restrict__ bm,
        const float* __restrict__ bih, const float* __restrict__ bhh,
        const float* __restrict__ b1, const float* __restrict__ b2,
        float* __restrict__ out){
    extern __shared__ __align__(16) float sm[];
    float* xs  = sm;
    float* hh  = xs + 1056;
    float* us  = hh + 1056;
    float* gi  = us + 1056;
    float* gh  = gi + 3104;
    float* hid = gh + 3104;
    __half* Wt = (__half*)(sm + 13504);   // 32x264 halfs
    __shared__ float dinv[NB];
    int tid = threadIdx.x, r0 = blockIdx.x*NB;

    if (mode == MODE_FIRST){
        float sig = sigma[0];
        for (int u = tid; u < 1024; u += 256){
            int j = u>>8, c = u&255, row = r0 + j;
            float wv = w0[(row % Kk)*256 + c];
            float v = wv + z[row*256 + c]*sig*wv;
            hh[j*264 + c] = v;
            g_slots[row*256 + c] = v;
        }
        __syncthreads();
        lnRow(hh, xs, gs, bs);
        mgemm16(xs, 264, g_Wqk16, 256, 256, g_qW + (size_t)r0*256, 256, nullptr, false, Wt);
        return;
    }

    if (tid < NB){
        float s = 0.f;
        #pragma unroll
        for (int p=0;p<NCHUNK;p++) s += __ldcg(&g_asum_part[(r0+tid)*NCHUNK + p]);
        dinv[tid] = 1.f/(s + 1e-6f);
    }
    __syncthreads();
    for (int u = tid; u < 1024; u += 256){
        float s = 0.f;
        #pragma unroll
        for (int p=0;p<NCHUNK;p++) s += __ldcg(&g_updFp[(size_t)p*RW*256 + (size_t)r0*256 + u]);
        int j = u>>8, c = u&255;
        xs[j*264 + c] = s * dinv[j];
        hh[j*264 + c] = g_slots[r0*256 + u];
    }
    __syncthreads();
    mgemm16(xs, 264, g_Wv16, 256, 256, us, 264, nullptr, false, Wt);
    mgemm16(us, 264, g_WihT16, 256, 768, gi, 776, bih, false, Wt);
    mgemm16(hh, 264, g_WhhT16, 256, 768, gh, 776, bhh, false, Wt);
    for (int u = tid; u < 1024; u += 256){
        int j = u>>8, c = u&255;
        float r  = 1.f/(1.f + __expf(-(gi[j*776 + c]     + gh[j*776 + c])));
        float zg = 1.f/(1.f + __expf(-(gi[j*776 + 256+c] + gh[j*776 + 256+c])));
        float nn = tanhf(gi[j*776 + 512+c] + r*gh[j*776 + 512+c]);
        hh[j*264 + c] = (1.f - zg)*nn + zg*hh[j*264 + c];
    }
    __syncthreads();
    lnRow(hh, xs, gm, bm);
    mgemm16(xs, 264, g_W116, 256, 1024, hid, 1032, b1, true, Wt);
    mgemm16(hid, 1032, g_W216, 1024, 256, us, 264, b2, false, Wt);
    for (int u = tid; u < 1024; u += 256){
        int j = u>>8, c = u&255;
        float v = hh[j*264 + c] + us[j*264 + c];
        hh[j*264 + c] = v;
        g_slots[r0*256 + u] = v;
        if (mode == MODE_LAST) out[r0*256 + u] = v;
    }
    __syncthreads();
    if (mode != MODE_LAST){
        lnRow(hh, xs, gs, bs);
        mgemm16(xs, 264, g_Wqk16, 256, 256, g_qW + (size_t)r0*256, 256, nullptr, false, Wt);
    }
}

// ---------------- host ----------------
extern "C" void kernel_launch(void* const* d_in, const int* in_sizes, int n_in,
                              void* d_out, int out_size){
    const float* features=(const float*)d_in[0];
    const float* sigma=(const float*)d_in[1];
    const float* z   =(const float*)d_in[2];
    const float* w0  =(const float*)d_in[3];
    const float* gf  =(const float*)d_in[4];  const float* bf =(const float*)d_in[5];
    const float* gs  =(const float*)d_in[6];  const float* bs =(const float*)d_in[7];
    const float* gm  =(const float*)d_in[8];  const float* bm =(const float*)d_in[9];
    const float* Wk  =(const float*)d_in[10]; const float* Wv =(const float*)d_in[11];
    const float* Wq  =(const float*)d_in[12];
    const float* Wih =(const float*)d_in[13]; const float* Whh=(const float*)d_in[14];
    const float* bih =(const float*)d_in[15]; const float* bhh=(const float*)d_in[16];
    const float* W1  =(const float*)d_in[17]; const float* b1 =(const float*)d_in[18];
    const float* W2  =(const float*)d_in[19]; const float* b2 =(const float*)d_in[20];
    float* out = (float*)d_out;

    const int paSmem = (128*FT_STRIDE + 16*FT_STRIDE + 16*AT_STRIDE)*2;  // 80,384 B
    const int k3Smem = 13504*4 + 32*264*2;                               // 70,912 B
    cudaFuncSetAttribute(passAB_k, cudaFuncAttributeMaxDynamicSharedMemorySize, paSmem);
    cudaFuncSetAttribute(k3_k,     cudaFuncAttributeMaxDynamicSharedMemorySize, k3Smem);

    static cudaStream_t s2 = nullptr;
    static cudaEvent_t  e0 = nullptr, e2 = nullptr;
    if (!s2){
        cudaStreamCreateWithFlags(&s2, cudaStreamNonBlocking);
        cudaEventCreateWithFlags(&e0, cudaEventDisableTiming);
        cudaEventCreateWithFlags(&e2, cudaEventDisableTiming);
    }

    // fork: weight prep chain on s2, LN on main stream (concurrent)
    cudaEventRecord(e0, 0);
    cudaStreamWaitEvent(s2, e0, 0);
    gemmT16_k<<<256,256,0,s2>>>(Wq, Wk);                                   // 0
    prep_k<<<1024,256,0,s2>>>(Wih, Whh, Wv, W1, W2);                       // 1
    ln_feat16_k<<<16384,256>>>(features, gf, bf);                          // 2 (main)
    k3_k<<<K3_BLOCKS,256,k3Smem,s2>>>(MODE_FIRST, z, w0, sigma, gs, bs, gm, bm,
                                      bih, bhh, b1, b2, out);              // 3 <- profiled
    cudaEventRecord(e2, s2);
    cudaStreamWaitEvent(0, e2, 0);

    passAB_k<<<dim3(Bsz,NCHUNK),256,paSmem>>>(out + SLOTS_ELEMS, 0);       // 4
    k3_k<<<K3_BLOCKS,256,k3Smem>>>(MODE_FULL, z, w0, sigma, gs, bs, gm, bm,
                                   bih, bhh, b1, b2, out);                 // 5
    passAB_k<<<dim3(Bsz,NCHUNK),256,paSmem>>>(out + SLOTS_ELEMS, 0);       // 6
    k3_k<<<K3_BLOCKS,256,k3Smem>>>(MODE_FULL, z, w0, sigma, gs, bs, gm, bm,
                                   bih, bhh, b1, b2, out);                 // 7
    passAB_k<<<dim3(Bsz,NCHUNK),256,paSmem>>>(out + SLOTS_ELEMS, 1);       // 8
    k3_k<<<K3_BLOCKS,256,k3Smem>>>(MODE_LAST, z, w0, sigma, gs, bs, gm, bm,
                                   bih, bhh, b1, b2, out);                 // 9
}